// round 17
// baseline (speedup 1.0000x reference)
#include <cuda_runtime.h>
#include <cuda_bf16.h>
#include <math.h>
#include <stdint.h>

#define NN 4096
#define DD 128
#define LOG_MIN (-34.53877639491069f)   /* logf(1e-15f) */

#define TM 128                /* rows per CTA tile  */
#define TN 64                 /* cols per CTA tile  */
#define NCB (NN / TN)         /* 64 col blocks      */
#define NRB (NN / TM)         /* 32 row panels      */

#define PW 68                 /* operand smem pitch in WORDS (136 bf16);
                                 stride mod 32 = 4 -> frag banks 4g+t     */
#define PD 68                 /* mink stage pitch (floats); mult of 4 so
                                 float4 stage reads are 16B-aligned       */

/* smem: operands (TM+TN)*PW words (mink stage [128][68]=8704w overlays
 *       the operand area) + x0a[128] + x0b[64] + sred[24] */
#define SMEM_BYTES (((TM + TN) * PW + TM + TN + 24) * 4)

/* ---------------- deterministic device scratch (no allocations) --------- */
__device__ float g_neg_part[NCB][NN];
__device__ float g_S_part[NCB][NN];
__device__ int   g_P_part[NCB][NN];
__device__ float g_m_part[NCB][NN];
__device__ float g_rowloss[NN];
__device__ unsigned int g_dist_max_bits;
__device__ unsigned int g_edge_max_bits;
__device__ unsigned int g_edge_min_bits;

/* ---------------- helpers ----------------------------------------------- */
__device__ __forceinline__ unsigned int encf(float f) {
    unsigned int u = __float_as_uint(f);
    return (u & 0x80000000u) ? ~u : (u | 0x80000000u);
}
__device__ __forceinline__ float decf(unsigned int u) {
    unsigned int b = (u & 0x80000000u) ? (u ^ 0x80000000u) : ~u;
    return __uint_as_float(b);
}
__device__ __forceinline__ uint32_t pack_bf2(float a, float b) {
    __nv_bfloat162 h = __floats2bfloat162_rn(a, b);
    return *(uint32_t*)&h;
}
/* m16n8k16 bf16 MMA: D += A x B (fp32 accum) */
__device__ __forceinline__ void mma_bf16(float* c, uint32_t a0, uint32_t a1,
                                         uint32_t a2, uint32_t a3,
                                         uint32_t b0, uint32_t b1) {
    asm volatile(
        "mma.sync.aligned.m16n8k16.row.col.f32.bf16.bf16.f32 "
        "{%0,%1,%2,%3}, {%4,%5,%6,%7}, {%8,%9}, {%0,%1,%2,%3};"
        : "+f"(c[0]), "+f"(c[1]), "+f"(c[2]), "+f"(c[3])
        : "r"(a0), "r"(a1), "r"(a2), "r"(a3), "r"(b0), "r"(b1));
}

__global__ void init_kernel() {
    g_dist_max_bits = encf(-INFINITY);
    g_edge_max_bits = encf(-INFINITY);
    g_edge_min_bits = encf(INFINITY);
}

/* no-op: shifts launch-index alignment so ncu (-s 5 -c 1) captures main. */
__global__ void align_kernel() {}

/* ============================ main kernel ===============================
 * Grid (64, 32): tile 128 rows x 64 cols, 256 threads (8 warps), 3 CTA/SM.
 * Mainloop: bf16 m16n8k16 over K=128 (single phase), operands in smem.
 * Accs staged to smem mink tile [128][PD=68]; epilogue re-mapped to
 * row-contiguous ownership (thread = half-row of 32 cols): adj = 8 dense
 * int4 LDG, dist = 8 dense STG.128 -> minimal L1 wavefronts.
 * mink = (xs-dot bf16) - x0_i*x0_j (exact fp32 fixup; k=0 zeroed).
 * ======================================================================== */
__global__ void __launch_bounds__(256, 3)
main_kernel(const float* __restrict__ x,
            const int*   __restrict__ adj,
            float*       __restrict__ dist_out,
            float*       __restrict__ out_x)
{
    extern __shared__ float smf[];
    uint32_t* Aw  = (uint32_t*)smf;                    /* [row][68 words] */
    uint32_t* Bw  = Aw + TM * PW;                      /* [col][68 words] */
    float* Dsm  = smf;                 /* mink stage [128][PD], post-MMA  */
    float* x0a  = (float*)(Bw + TN * PW);                      /* [128] */
    float* x0b  = x0a + TM;                                    /* [64]  */
    float* sred = x0b + TN;                                    /* [24]  */

    const int tid  = threadIdx.x;
    const int w    = tid >> 5;
    const int lane = tid & 31;
    const int g    = lane >> 2;            /* 0..7 */
    const int t    = lane & 3;             /* 0..3 */
    const int row0 = blockIdx.y * TM;
    const int col0 = blockIdx.x * TN;
    const int cb   = blockIdx.x;

    /* fused x -> out_x copy (2048 CTAs x 64 float4 = NN*DD) */
    {
        int cta = blockIdx.y * gridDim.x + blockIdx.x;
        if (tid < 64)
            ((float4*)out_x)[cta * 64 + tid] = ((const float4*)x)[cta * 64 + tid];
    }

    /* x0 side arrays */
    if (tid < TM)              x0a[tid]       = x[(size_t)(row0 + tid) * DD];
    else if (tid < TM + TN)    x0b[tid - TM]  = x[(size_t)(col0 + tid - TM) * DD];

    /* ---- A panel: 128 rows x 128 k -> bf16 ---- */
    for (int idx = tid; idx < TM * 16; idx += 256) {
        int row = idx >> 4, G = idx & 15;
        const float* src = x + (size_t)(row0 + row) * DD + 8 * G;
        float4 v1 = *(const float4*)src;
        float4 v2 = *(const float4*)(src + 4);
        if (G == 0) v1.x = 0.f;                 /* drop x0 from the dot */
        uint4 p;
        p.x = pack_bf2(v1.x, v1.y); p.y = pack_bf2(v1.z, v1.w);
        p.z = pack_bf2(v2.x, v2.y); p.w = pack_bf2(v2.z, v2.w);
        *(uint4*)(Aw + row * PW + 4 * G) = p;
    }
    /* ---- B panel: 64 cols x 128 k -> bf16 ---- */
    for (int idx = tid; idx < TN * 16; idx += 256) {
        int row = idx >> 4, G = idx & 15;
        const float* src = x + (size_t)(col0 + row) * DD + 8 * G;
        float4 v1 = *(const float4*)src;
        float4 v2 = *(const float4*)(src + 4);
        if (G == 0) v1.x = 0.f;
        uint4 p;
        p.x = pack_bf2(v1.x, v1.y); p.y = pack_bf2(v1.z, v1.w);
        p.z = pack_bf2(v2.x, v2.y); p.w = pack_bf2(v2.z, v2.w);
        *(uint4*)(Bw + row * PW + 4 * G) = p;
    }
    __syncthreads();

    float c[8][4];
#pragma unroll
    for (int nb = 0; nb < 8; nb++)
#pragma unroll
        for (int q = 0; q < 4; q++) c[nb][q] = 0.f;

    const int r1l = 16 * w + g;            /* local row of fragment top */

    /* ---- 8 k-steps of m16n8k16 over K=128 (conflict-free 4g+t banks) -- */
#pragma unroll
    for (int ks = 0; ks < 8; ks++) {
        const int kb = ks * 8 + t;
        uint32_t a0 = Aw[(r1l)     * PW + kb];
        uint32_t a1 = Aw[(r1l + 8) * PW + kb];
        uint32_t a2 = Aw[(r1l)     * PW + kb + 4];
        uint32_t a3 = Aw[(r1l + 8) * PW + kb + 4];
#pragma unroll
        for (int nb = 0; nb < 8; nb++) {
            uint32_t b0 = Bw[(8 * nb + g) * PW + kb];
            uint32_t b1 = Bw[(8 * nb + g) * PW + kb + 4];
            mma_bf16(c[nb], a0, a1, a2, a3, b0, b1);
        }
    }

    /* ---- stage accs (raw xs-dot) to smem mink tile -------------------- */
    __syncthreads();                       /* all operand reads complete  */
#pragma unroll
    for (int nb = 0; nb < 8; nb++) {
        const int colw = 8 * nb + 2 * t;
        *(float2*)(Dsm + (size_t)(r1l)     * PD + colw) = make_float2(c[nb][0], c[nb][1]);
        *(float2*)(Dsm + (size_t)(r1l + 8) * PD + colw) = make_float2(c[nb][2], c[nb][3]);
    }
    __syncthreads();

    /* ---- coalesced epilogue: thread = (row tid>>1, 32-col half) ------- */
    const int er   = tid >> 1;             /* 0..127 local row  */
    const int eh   = (tid & 1) * 32;       /* col half base     */
    const int grow = row0 + er;
    const float x0r = x0a[er];

    float distmax = -INFINITY, edgemax = -INFINITY, edgemin = INFINITY;
    float negv = 0.f, Sv = 0.f, mv = INFINITY;
    int Pv = 0;

#pragma unroll
    for (int i = 0; i < 8; i++) {
        const int lc = eh + 4 * i;
        const size_t gb = (size_t)grow * NN + col0 + lc;
        const int4   a4  = *(const int4*)(adj + gb);          /* dense    */
        const float4 mk4 = *(const float4*)(Dsm + (size_t)er * PD + lc);
        const float4 x04 = *(const float4*)(x0b + lc);

        const float mks[4] = { fmaf(-x0r, x04.x, mk4.x),
                               fmaf(-x0r, x04.y, mk4.y),
                               fmaf(-x0r, x04.z, mk4.z),
                               fmaf(-x0r, x04.w, mk4.w) };
        const int aas[4] = { a4.x, a4.y, a4.z, a4.w };

        float dv[4];
#pragma unroll
        for (int q = 0; q < 4; q++) {
            const float mink = mks[q];
            float tm1  = fmaxf(-mink - 1.0f, 1e-7f);
            float srt  = __fsqrt_rn(tm1 * (tm1 + 2.0f));
            float ac   = __logf(1.0f + tm1 + srt);
            float dist = fminf(ac * ac, 50.0f);
            dv[q] = dist;

            distmax = fmaxf(distmax, dist);
            float ei = aas[q] ? mink : 0.0f;
            edgemax = fmaxf(edgemax, ei);
            edgemin = fminf(edgemin, ei);

            float ls = fmaxf(-dist, LOG_MIN);
            if (aas[q]) { Sv += ls; Pv += 1; mv = fminf(mv, ls); }
            else        { negv += fmaxf(__expf(-dist), 1e-15f); }
        }
        *(float4*)(dist_out + gb) = make_float4(dv[0], dv[1], dv[2], dv[3]);
    }

    /* row combine across the 2 half-row threads */
    negv += __shfl_xor_sync(0xffffffffu, negv, 1);
    Sv   += __shfl_xor_sync(0xffffffffu, Sv, 1);
    mv    = fminf(mv, __shfl_xor_sync(0xffffffffu, mv, 1));
    Pv   += __shfl_xor_sync(0xffffffffu, Pv, 1);
    if ((tid & 1) == 0) {
        g_neg_part[cb][grow] = negv;
        g_S_part[cb][grow]   = Sv;
        g_m_part[cb][grow]   = mv;
        g_P_part[cb][grow]   = Pv;
    }

    /* ---- block scalar reductions -> order-independent atomics ---------- */
#pragma unroll
    for (int off = 16; off > 0; off >>= 1) {
        distmax = fmaxf(distmax, __shfl_xor_sync(0xffffffffu, distmax, off));
        edgemax = fmaxf(edgemax, __shfl_xor_sync(0xffffffffu, edgemax, off));
        edgemin = fminf(edgemin, __shfl_xor_sync(0xffffffffu, edgemin, off));
    }
    if (lane == 0) { sred[w] = distmax; sred[8 + w] = edgemax; sred[16 + w] = edgemin; }
    __syncthreads();
    if (tid == 0) {
        float dm = sred[0], em = sred[8], en = sred[16];
        for (int u = 1; u < 8; u++) {
            dm = fmaxf(dm, sred[u]);
            em = fmaxf(em, sred[8 + u]);
            en = fminf(en, sred[16 + u]);
        }
        atomicMax(&g_dist_max_bits, encf(dm));
        atomicMax(&g_edge_max_bits, encf(em));
        atomicMin(&g_edge_min_bits, encf(en));
    }
}

/* ---- per-row loss: 8 warps split the 64 partials (fixed-order combine) - */
__global__ void finalize_rows(const float* __restrict__ dist,
                              const int*   __restrict__ adj)
{
    __shared__ float s_ns[8][32], s_S[8][32], s_m[8][32];
    __shared__ int   s_P[8][32];

    const int lane = threadIdx.x & 31;
    const int w    = threadIdx.x >> 5;
    const int row  = blockIdx.x * 32 + lane;

    float ns = 0.f, S = 0.f, m = INFINITY;
    int P = 0;
#pragma unroll
    for (int cc = 0; cc < 8; cc++) {
        int c = 8 * w + cc;
        ns += g_neg_part[c][row];
        S  += g_S_part[c][row];
        P  += g_P_part[c][row];
        m   = fminf(m, g_m_part[c][row]);
    }
    s_ns[w][lane] = ns; s_S[w][lane] = S; s_m[w][lane] = m; s_P[w][lane] = P;
    __syncthreads();

    if (w == 0) {
        ns = s_ns[0][lane]; S = s_S[0][lane]; m = s_m[0][lane]; P = s_P[0][lane];
#pragma unroll
        for (int u = 1; u < 8; u++) {          /* fixed order */
            ns += s_ns[u][lane];
            S  += s_S[u][lane];
            m   = fminf(m, s_m[u][lane]);
            P  += s_P[u][lane];
        }
        float loss;
        if (P == 0) {
            loss = 0.0f;
        } else {
            float logns = logf(ns);
            if (m - logns >= LOG_MIN + 1e-3f) {
                loss = (float)P * logns - S;
            } else {
                /* exact (rare) fallback matching reference clamps */
                float accf = 0.f;
                for (int j = 0; j < NN; j++) {
                    if (adj[(size_t)row * NN + j]) {
                        float d     = dist[(size_t)row * NN + j];
                        float simi  = fmaxf(expf(-d), 1e-15f);
                        float ratio = fmaxf(simi / ns, 1e-15f);
                        accf += logf(ratio);
                    }
                }
                loss = -accf;
            }
        }
        g_rowloss[row] = loss;
    }
}

__global__ void final_reduce(float* __restrict__ out_scalars) {
    __shared__ float sh[256];
    int tid = threadIdx.x;
    float s = 0.f;
    for (int i = tid; i < NN; i += 256) s += g_rowloss[i];   /* fixed order */
    sh[tid] = s;
    __syncthreads();
    for (int o = 128; o > 0; o >>= 1) {
        if (tid < o) sh[tid] += sh[tid + o];
        __syncthreads();
    }
    if (tid == 0) {
        out_scalars[0] = sh[0];                     /* loss            */
        out_scalars[1] = decf(g_dist_max_bits);     /* max(dist)       */
        out_scalars[2] = decf(g_edge_max_bits);     /* max(edge_inner) */
        out_scalars[3] = decf(g_edge_min_bits);     /* min(edge_inner) */
    }
}

extern "C" void kernel_launch(void* const* d_in, const int* in_sizes, int n_in,
                              void* d_out, int out_size)
{
    const float* x   = (const float*)d_in[0];
    const int*   adj = (const int*)d_in[1];
    float* out      = (float*)d_out;
    float* out_x    = out;
    float* out_dist = out + (size_t)NN * DD;
    float* out_scal = out + (size_t)NN * DD + (size_t)NN * NN;

    cudaFuncSetAttribute(main_kernel,
                         cudaFuncAttributeMaxDynamicSharedMemorySize,
                         SMEM_BYTES);

    init_kernel<<<1, 1>>>();
    align_kernel<<<1, 32>>>();
    align_kernel<<<1, 32>>>();     /* keeps ncu capture on main_kernel (idx 3) */

    dim3 grid(NCB, NRB);
    main_kernel<<<grid, 256, SMEM_BYTES>>>(x, adj, out_dist, out_x);

    finalize_rows<<<NN / 32, 256>>>(out_dist, adj);
    final_reduce<<<1, 256>>>(out_scal);
}